// round 11
// baseline (speedup 1.0000x reference)
#include <cuda_runtime.h>
#include <math.h>

// Problem constants
#define TOK   4096   // B*L = 2*2048
#define DIMK  1024
#define HQ    16
#define HKV   4
#define HD    64
#define LSEQ  2048

// Scratch (static device globals — allocation-free)
__device__ float g_q [TOK * HQ  * HD];   // 16 MB  [token][h*64+d]
__device__ float g_k [TOK * HKV * HD];   //  4 MB  [token][kv*64+d]
__device__ float g_v [TOK * HKV * HD];   //  4 MB
__device__ float g_ao[TOK * HQ  * HD];   // 16 MB  attention output

// ---------------------------------------------------------------------------
// 128x128 tile SGEMM body, C[m,n] = sum_k A[m,k]*B[n,k]  (NT, both row-major,
// K contiguous). BK=16, 256 threads, 8x8 per thread with 4+4 split fragments.
// Requires: M,N tiles exactly 128, K % 16 == 0. No bounds checks needed here.
// ---------------------------------------------------------------------------
__device__ __forceinline__ void gemm128(const float* __restrict__ Ag,   // A + bm*K
                                        const float* __restrict__ Bg,   // B + bn*K
                                        float*       __restrict__ Cg,   // C + bm*ldc + bn
                                        int K, int ldc)
{
    __shared__ float As[16][128];
    __shared__ float Bs[16][128];

    const int tid  = threadIdx.x;       // 0..255
    const int lrow = tid >> 2;          // 0..63
    const int lseg = (tid & 3) << 2;    // 0,4,8,12
    const int tx   = tid & 15;
    const int ty   = tid >> 4;

    float acc[8][8];
#pragma unroll
    for (int i = 0; i < 8; i++)
#pragma unroll
        for (int j = 0; j < 8; j++) acc[i][j] = 0.0f;

    const float* A0 = Ag + (size_t)lrow        * K + lseg;
    const float* A1 = Ag + (size_t)(lrow + 64) * K + lseg;
    const float* B0 = Bg + (size_t)lrow        * K + lseg;
    const float* B1 = Bg + (size_t)(lrow + 64) * K + lseg;

    for (int k0 = 0; k0 < K; k0 += 16) {
        float4 a0 = *(const float4*)(A0 + k0);
        float4 a1 = *(const float4*)(A1 + k0);
        float4 b0 = *(const float4*)(B0 + k0);
        float4 b1 = *(const float4*)(B1 + k0);

        __syncthreads();   // previous iteration's compute done before overwrite
        As[lseg + 0][lrow]      = a0.x; As[lseg + 1][lrow]      = a0.y;
        As[lseg + 2][lrow]      = a0.z; As[lseg + 3][lrow]      = a0.w;
        As[lseg + 0][lrow + 64] = a1.x; As[lseg + 1][lrow + 64] = a1.y;
        As[lseg + 2][lrow + 64] = a1.z; As[lseg + 3][lrow + 64] = a1.w;
        Bs[lseg + 0][lrow]      = b0.x; Bs[lseg + 1][lrow]      = b0.y;
        Bs[lseg + 2][lrow]      = b0.z; Bs[lseg + 3][lrow]      = b0.w;
        Bs[lseg + 0][lrow + 64] = b1.x; Bs[lseg + 1][lrow + 64] = b1.y;
        Bs[lseg + 2][lrow + 64] = b1.z; Bs[lseg + 3][lrow + 64] = b1.w;
        __syncthreads();

#pragma unroll
        for (int kk = 0; kk < 16; kk++) {
            float4 av0 = *(const float4*)(&As[kk][ty * 4]);
            float4 av1 = *(const float4*)(&As[kk][ty * 4 + 64]);
            float4 bv0 = *(const float4*)(&Bs[kk][tx * 4]);
            float4 bv1 = *(const float4*)(&Bs[kk][tx * 4 + 64]);
            float a[8] = {av0.x, av0.y, av0.z, av0.w, av1.x, av1.y, av1.z, av1.w};
            float b[8] = {bv0.x, bv0.y, bv0.z, bv0.w, bv1.x, bv1.y, bv1.z, bv1.w};
#pragma unroll
            for (int i = 0; i < 8; i++)
#pragma unroll
                for (int j = 0; j < 8; j++)
                    acc[i][j] = fmaf(a[i], b[j], acc[i][j]);
        }
    }

#pragma unroll
    for (int i = 0; i < 8; i++) {
        int m = ty * 4 + (i & 3) + ((i >> 2) << 6);   // 4+4 split rows
        float4 c0 = make_float4(acc[i][0], acc[i][1], acc[i][2], acc[i][3]);
        float4 c1 = make_float4(acc[i][4], acc[i][5], acc[i][6], acc[i][7]);
        *(float4*)(Cg + (size_t)m * ldc + tx * 4)      = c0;
        *(float4*)(Cg + (size_t)m * ldc + tx * 4 + 64) = c1;
    }
}

// ---------------------------------------------------------------------------
// Fused QKV projection: one launch, grid (12, 32).
// N-blocks 0..7 -> q (ldc 1024), 8..9 -> k (ldc 256), 10..11 -> v (ldc 256).
// ---------------------------------------------------------------------------
__global__ void __launch_bounds__(256, 2)
qkv_kernel(const float* __restrict__ x,  const float* __restrict__ wq,
           const float* __restrict__ wk, const float* __restrict__ wv)
{
    const int nb = blockIdx.x;
    const int mb = blockIdx.y;
    const float* Bg;
    float* Cg;
    int ldc;
    if (nb < 8) {
        Bg  = wq + (size_t)nb * 128 * DIMK;
        Cg  = g_q + (size_t)mb * 128 * 1024 + nb * 128;
        ldc = 1024;
    } else if (nb < 10) {
        int t = nb - 8;
        Bg  = wk + (size_t)t * 128 * DIMK;
        Cg  = g_k + (size_t)mb * 128 * 256 + t * 128;
        ldc = 256;
    } else {
        int t = nb - 10;
        Bg  = wv + (size_t)t * 128 * DIMK;
        Cg  = g_v + (size_t)mb * 128 * 256 + t * 128;
        ldc = 256;
    }
    gemm128(x + (size_t)mb * 128 * DIMK, Bg, Cg, DIMK, ldc);
}

// ---------------------------------------------------------------------------
// Output projection: out = g_ao @ wo^T, grid (8, 32).
// ---------------------------------------------------------------------------
__global__ void __launch_bounds__(256, 2)
oproj_kernel(const float* __restrict__ wo, float* __restrict__ out)
{
    gemm128(g_ao + (size_t)blockIdx.y * 128 * 1024,
            wo   + (size_t)blockIdx.x * 128 * DIMK,
            out  + (size_t)blockIdx.y * 128 * 1024 + blockIdx.x * 128,
            DIMK, 1024);
}

// ---------------------------------------------------------------------------
// Per-head RMSNorm: one warp per (token, head) of 64 values.
// which==0 -> g_q (outScale folds in softmax 1/sqrt(64)), which==1 -> g_k.
// norm = rsqrt(mean(x^2) + 0.01); out = x * norm * w * outScale
// ---------------------------------------------------------------------------
__global__ void rmsnorm_kernel(const float* __restrict__ w, int which,
                               int total, float outScale)
{
    int wp = (blockIdx.x * blockDim.x + threadIdx.x) >> 5;
    if (wp >= total) return;
    int lane = threadIdx.x & 31;
    float* p = (which == 0 ? g_q : g_k) + (size_t)wp * 64 + lane * 2;
    float2 v = *(float2*)p;
    float ss = v.x * v.x + v.y * v.y;
#pragma unroll
    for (int o = 16; o > 0; o >>= 1) ss += __shfl_xor_sync(0xffffffffu, ss, o);
    float norm = rsqrtf(ss * (1.0f / 64.0f) + 0.01f) * outScale;
    float2 wv = *(const float2*)(w + lane * 2);
    v.x *= norm * wv.x;
    v.y *= norm * wv.y;
    *(float2*)p = v;
}

// ---------------------------------------------------------------------------
// Sliding-window ALiBi attention. WINDOW=16 => each query sees <=17 keys.
// One warp handles 4 consecutive queries of one (b,h): union key window
// [i0-16, i0+3] loaded once per j. Online softmax fully in registers.
// Each lane owns 2 of the 64 head dims; dot via 5x shfl_xor.
// q already carries the 1/sqrt(64) scale (folded in rmsnorm).
// ---------------------------------------------------------------------------
__global__ void attn_kernel()
{
    int gw   = (blockIdx.x * blockDim.x + threadIdx.x) >> 5;  // 0..16383
    int lane = threadIdx.x & 31;
    int b  = gw >> 13;               // 8192 warps per batch
    int h  = (gw >> 9) & 15;
    int i0 = (gw & 511) << 2;        // first of 4 queries
    int kvh = h & 3;                 // GQA: head h -> kv head h % 4

    float slope = exp2f(-0.5f * (float)(h + 1));   // ALiBi slope 2^{-(h+1)/2}

    const float* qp = g_q + ((size_t)(b * LSEQ + i0) * 1024) + h * 64 + lane * 2;
    float2 qv[4];
#pragma unroll
    for (int t = 0; t < 4; t++) qv[t] = *(const float2*)(qp + t * 1024);

    const float* kp = g_k + (size_t)b * LSEQ * 256 + kvh * 64 + lane * 2;
    const float* vp = g_v + (size_t)b * LSEQ * 256 + kvh * 64 + lane * 2;

    float m[4], l[4], ax[4], ay[4];
#pragma unroll
    for (int t = 0; t < 4; t++) { m[t] = -1e30f; l[t] = 0.f; ax[t] = 0.f; ay[t] = 0.f; }

    int jlo = i0 - 16; if (jlo < 0) jlo = 0;
    for (int j = jlo; j <= i0 + 3; j++) {
        float2 kk = *(const float2*)(kp + (size_t)j * 256);
        float2 vv = *(const float2*)(vp + (size_t)j * 256);
#pragma unroll
        for (int t = 0; t < 4; t++) {
            int i = i0 + t;
            if (j > i || j < i - 16) continue;   // warp-uniform predicate
            float s = qv[t].x * kk.x + qv[t].y * kk.y;
#pragma unroll
            for (int o = 16; o > 0; o >>= 1) s += __shfl_xor_sync(0xffffffffu, s, o);
            s += slope * (float)(j - i);         // ALiBi bias (<= 0)
            float mn = fmaxf(m[t], s);
            float c  = __expf(m[t] - mn);
            float p  = __expf(s - mn);
            l[t]  = l[t]  * c + p;
            ax[t] = ax[t] * c + p * vv.x;
            ay[t] = ay[t] * c + p * vv.y;
            m[t]  = mn;
        }
    }

    float* op = g_ao + ((size_t)(b * LSEQ + i0) * 1024) + h * 64 + lane * 2;
#pragma unroll
    for (int t = 0; t < 4; t++) {
        float inv = 1.0f / l[t];
        *(float2*)(op + t * 1024) = make_float2(ax[t] * inv, ay[t] * inv);
    }
}

// ---------------------------------------------------------------------------
// Launch sequence (graph-capturable: kernel launches only, default stream)
// Inputs: 0=x, 1=wq, 2=wk, 3=wv, 4=wo, 5=q_norm_w, 6=k_norm_w
// ---------------------------------------------------------------------------
extern "C" void kernel_launch(void* const* d_in, const int* in_sizes, int n_in,
                              void* d_out, int out_size)
{
    const float* x   = (const float*)d_in[0];
    const float* wq  = (const float*)d_in[1];
    const float* wk  = (const float*)d_in[2];
    const float* wv  = (const float*)d_in[3];
    const float* wo  = (const float*)d_in[4];
    const float* qnw = (const float*)d_in[5];
    const float* knw = (const float*)d_in[6];
    float* out = (float*)d_out;

    // 1) QKV projection (fused): grid (12, 32)
    qkv_kernel<<<dim3(12, 32), 256>>>(x, wq, wk, wv);

    // 2) RMSNorm q (folds attention scale 1/8) : 4096*16 warps
    rmsnorm_kernel<<<(TOK * HQ * 32) / 256, 256>>>(qnw, 0, TOK * HQ, 0.125f);

    // 3) RMSNorm k : 4096*4 warps
    rmsnorm_kernel<<<(TOK * HKV * 32) / 256, 256>>>(knw, 1, TOK * HKV, 1.0f);

    // 4) Sliding-window ALiBi attention: 16384 warps (4 queries each)
    attn_kernel<<<2048, 256>>>();

    // 5) Output projection: grid (8, 32)
    oproj_kernel<<<dim3(8, 32), 256>>>(wo, out);
}

// round 12
// speedup vs baseline: 2.1130x; 2.1130x over previous
#include <cuda_runtime.h>
#include <math.h>

// Problem constants
#define TOK   4096   // B*L = 2*2048
#define DIMK  1024
#define HQ    16
#define HKV   4
#define HD    64
#define LSEQ  2048

// Scratch (static device globals — allocation-free)
__device__ float g_q [TOK * HQ  * HD];   // 16 MB  [token][h*64+d]
__device__ float g_k [TOK * HKV * HD];   //  4 MB  [token][kv*64+d]
__device__ float g_v [TOK * HKV * HD];   //  4 MB
__device__ float g_ao[TOK * HQ  * HD];   // 16 MB  attention output

// ---------------------------------------------------------------------------
// tf32 helpers
// ---------------------------------------------------------------------------
__device__ __forceinline__ unsigned f2tf(float f) {
    unsigned r;
    asm("cvt.rna.tf32.f32 %0, %1;" : "=r"(r) : "f"(f));
    return r;
}

__device__ __forceinline__ void mma_tf32(float& c0, float& c1, float& c2, float& c3,
                                         unsigned a0, unsigned a1, unsigned a2, unsigned a3,
                                         unsigned b0, unsigned b1)
{
    asm volatile(
        "mma.sync.aligned.m16n8k8.row.col.f32.tf32.tf32.f32 "
        "{%0,%1,%2,%3}, {%4,%5,%6,%7}, {%8,%9}, {%0,%1,%2,%3};"
        : "+f"(c0), "+f"(c1), "+f"(c2), "+f"(c3)
        : "r"(a0), "r"(a1), "r"(a2), "r"(a3), "r"(b0), "r"(b1));
}

// ---------------------------------------------------------------------------
// 128x128 tile GEMM on tensor cores (tf32), C[m,n] = sum_k A[m,k]*B[n,k]
// (NT, both operands row-major with K contiguous). BK=32, 256 threads,
// 8 warps in a 4x2 grid, each warp computes 32x64 via 2x8 m16n8k8 tiles.
// Requires tiles exactly 128x128 and K % 32 == 0 (always true here).
// ---------------------------------------------------------------------------
#define SROW 36   // padded row stride (words); 36*4B=144B keeps 16B alignment
                  // and makes frag-load banks = (4*g + tig) % 32 -> conflict-free

__device__ __forceinline__ void gemm128_tc(const float* __restrict__ Ag,
                                           const float* __restrict__ Bg,
                                           float*       __restrict__ Cg,
                                           int K, int ldc)
{
    __shared__ __align__(16) unsigned As[128 * SROW];
    __shared__ __align__(16) unsigned Bs[128 * SROW];

    const int tid    = threadIdx.x;
    const int lane   = tid & 31;
    const int wid    = tid >> 5;
    const int warp_m = (wid & 3) * 32;   // 0,32,64,96
    const int warp_n = (wid >> 2) * 64;  // 0,64
    const int g      = lane >> 2;        // 0..7
    const int tig    = lane & 3;         // 0..3

    float acc[2][8][4];
#pragma unroll
    for (int mt = 0; mt < 2; mt++)
#pragma unroll
        for (int nt = 0; nt < 8; nt++)
#pragma unroll
            for (int c = 0; c < 4; c++) acc[mt][nt][c] = 0.0f;

    // Staging: each thread owns 16 consecutive floats of one row per operand.
    const int srow = tid >> 1;             // 0..127
    const int sc0  = (tid & 1) * 16;       // 0 or 16
    const float* Aptr = Ag + (size_t)srow * K + sc0;
    const float* Bptr = Bg + (size_t)srow * K + sc0;
    unsigned* Asm = &As[srow * SROW + sc0];
    unsigned* Bsm = &Bs[srow * SROW + sc0];

    float4 ra[4], rb[4];
#pragma unroll
    for (int i = 0; i < 4; i++) {
        ra[i] = *(const float4*)(Aptr + i * 4);
        rb[i] = *(const float4*)(Bptr + i * 4);
    }

    for (int k0 = 0; k0 < K; k0 += 32) {
        // Convert staged fp32 -> tf32 bits and store to smem
#pragma unroll
        for (int i = 0; i < 4; i++) {
            uint4 ta = make_uint4(f2tf(ra[i].x), f2tf(ra[i].y), f2tf(ra[i].z), f2tf(ra[i].w));
            uint4 tb = make_uint4(f2tf(rb[i].x), f2tf(rb[i].y), f2tf(rb[i].z), f2tf(rb[i].w));
            *(uint4*)(Asm + i * 4) = ta;
            *(uint4*)(Bsm + i * 4) = tb;
        }
        __syncthreads();

        // Prefetch next K-slab (issued before the MMA section to hide latency)
        if (k0 + 32 < K) {
#pragma unroll
            for (int i = 0; i < 4; i++) {
                ra[i] = *(const float4*)(Aptr + k0 + 32 + i * 4);
                rb[i] = *(const float4*)(Bptr + k0 + 32 + i * 4);
            }
        }

        // Compute 4 k-steps of 8
#pragma unroll
        for (int ks = 0; ks < 4; ks++) {
            const int kk = ks * 8;
            unsigned a[2][4];
#pragma unroll
            for (int mt = 0; mt < 2; mt++) {
                const int mr = warp_m + mt * 16 + g;
                a[mt][0] = As[mr * SROW + kk + tig];
                a[mt][1] = As[(mr + 8) * SROW + kk + tig];
                a[mt][2] = As[mr * SROW + kk + tig + 4];
                a[mt][3] = As[(mr + 8) * SROW + kk + tig + 4];
            }
#pragma unroll
            for (int nt = 0; nt < 8; nt++) {
                const int nr = warp_n + nt * 8 + g;
                const unsigned b0 = Bs[nr * SROW + kk + tig];
                const unsigned b1 = Bs[nr * SROW + kk + tig + 4];
                mma_tf32(acc[0][nt][0], acc[0][nt][1], acc[0][nt][2], acc[0][nt][3],
                         a[0][0], a[0][1], a[0][2], a[0][3], b0, b1);
                mma_tf32(acc[1][nt][0], acc[1][nt][1], acc[1][nt][2], acc[1][nt][3],
                         a[1][0], a[1][1], a[1][2], a[1][3], b0, b1);
            }
        }
        __syncthreads();
    }

    // Epilogue: c0/c1 at (g, 2*tig / +1), c2/c3 at (g+8, ...)
#pragma unroll
    for (int mt = 0; mt < 2; mt++) {
#pragma unroll
        for (int nt = 0; nt < 8; nt++) {
            const int r0 = warp_m + mt * 16 + g;
            const int c  = warp_n + nt * 8 + tig * 2;
            *(float2*)(Cg + (size_t)r0 * ldc + c)       = make_float2(acc[mt][nt][0], acc[mt][nt][1]);
            *(float2*)(Cg + (size_t)(r0 + 8) * ldc + c) = make_float2(acc[mt][nt][2], acc[mt][nt][3]);
        }
    }
}

// ---------------------------------------------------------------------------
// Fused QKV projection: grid (12, 32). N-blocks 0..7 -> q, 8..9 -> k, 10..11 -> v.
// ---------------------------------------------------------------------------
__global__ void __launch_bounds__(256, 2)
qkv_kernel(const float* __restrict__ x,  const float* __restrict__ wq,
           const float* __restrict__ wk, const float* __restrict__ wv)
{
    const int nb = blockIdx.x;
    const int mb = blockIdx.y;
    const float* Bg;
    float* Cg;
    int ldc;
    if (nb < 8) {
        Bg  = wq + (size_t)nb * 128 * DIMK;
        Cg  = g_q + (size_t)mb * 128 * 1024 + nb * 128;
        ldc = 1024;
    } else if (nb < 10) {
        int t = nb - 8;
        Bg  = wk + (size_t)t * 128 * DIMK;
        Cg  = g_k + (size_t)mb * 128 * 256 + t * 128;
        ldc = 256;
    } else {
        int t = nb - 10;
        Bg  = wv + (size_t)t * 128 * DIMK;
        Cg  = g_v + (size_t)mb * 128 * 256 + t * 128;
        ldc = 256;
    }
    gemm128_tc(x + (size_t)mb * 128 * DIMK, Bg, Cg, DIMK, ldc);
}

// ---------------------------------------------------------------------------
// Output projection: out = g_ao @ wo^T, grid (8, 32).
// ---------------------------------------------------------------------------
__global__ void __launch_bounds__(256, 2)
oproj_kernel(const float* __restrict__ wo, float* __restrict__ out)
{
    gemm128_tc(g_ao + (size_t)blockIdx.y * 128 * 1024,
               wo   + (size_t)blockIdx.x * 128 * DIMK,
               out  + (size_t)blockIdx.y * 128 * 1024 + blockIdx.x * 128,
               DIMK, 1024);
}

// ---------------------------------------------------------------------------
// Per-head RMSNorm: one warp per (token, head) of 64 values.
// which==0 -> g_q (outScale folds in softmax 1/sqrt(64)), which==1 -> g_k.
// ---------------------------------------------------------------------------
__global__ void rmsnorm_kernel(const float* __restrict__ w, int which,
                               int total, float outScale)
{
    int wp = (blockIdx.x * blockDim.x + threadIdx.x) >> 5;
    if (wp >= total) return;
    int lane = threadIdx.x & 31;
    float* p = (which == 0 ? g_q : g_k) + (size_t)wp * 64 + lane * 2;
    float2 v = *(float2*)p;
    float ss = v.x * v.x + v.y * v.y;
#pragma unroll
    for (int o = 16; o > 0; o >>= 1) ss += __shfl_xor_sync(0xffffffffu, ss, o);
    float norm = rsqrtf(ss * (1.0f / 64.0f) + 0.01f) * outScale;
    float2 wv = *(const float2*)(w + lane * 2);
    v.x *= norm * wv.x;
    v.y *= norm * wv.y;
    *(float2*)p = v;
}

// ---------------------------------------------------------------------------
// Sliding-window ALiBi attention (unchanged from passing R9 kernel).
// One warp handles 4 consecutive queries of one (b,h). Online softmax in
// registers; each lane owns 2 of 64 head dims; dot via 5x shfl_xor.
// ---------------------------------------------------------------------------
__global__ void attn_kernel()
{
    int gw   = (blockIdx.x * blockDim.x + threadIdx.x) >> 5;  // 0..16383
    int lane = threadIdx.x & 31;
    int b  = gw >> 13;               // 8192 warps per batch
    int h  = (gw >> 9) & 15;
    int i0 = (gw & 511) << 2;        // first of 4 queries
    int kvh = h & 3;                 // GQA: head h -> kv head h % 4

    float slope = exp2f(-0.5f * (float)(h + 1));   // ALiBi slope 2^{-(h+1)/2}

    const float* qp = g_q + ((size_t)(b * LSEQ + i0) * 1024) + h * 64 + lane * 2;
    float2 qv[4];
#pragma unroll
    for (int t = 0; t < 4; t++) qv[t] = *(const float2*)(qp + t * 1024);

    const float* kp = g_k + (size_t)b * LSEQ * 256 + kvh * 64 + lane * 2;
    const float* vp = g_v + (size_t)b * LSEQ * 256 + kvh * 64 + lane * 2;

    float m[4], l[4], ax[4], ay[4];
#pragma unroll
    for (int t = 0; t < 4; t++) { m[t] = -1e30f; l[t] = 0.f; ax[t] = 0.f; ay[t] = 0.f; }

    int jlo = i0 - 16; if (jlo < 0) jlo = 0;
    for (int j = jlo; j <= i0 + 3; j++) {
        float2 kk = *(const float2*)(kp + (size_t)j * 256);
        float2 vv = *(const float2*)(vp + (size_t)j * 256);
#pragma unroll
        for (int t = 0; t < 4; t++) {
            int i = i0 + t;
            if (j > i || j < i - 16) continue;   // warp-uniform predicate
            float s = qv[t].x * kk.x + qv[t].y * kk.y;
#pragma unroll
            for (int o = 16; o > 0; o >>= 1) s += __shfl_xor_sync(0xffffffffu, s, o);
            s += slope * (float)(j - i);         // ALiBi bias (<= 0)
            float mn = fmaxf(m[t], s);
            float c  = __expf(m[t] - mn);
            float p  = __expf(s - mn);
            l[t]  = l[t]  * c + p;
            ax[t] = ax[t] * c + p * vv.x;
            ay[t] = ay[t] * c + p * vv.y;
            m[t]  = mn;
        }
    }

    float* op = g_ao + ((size_t)(b * LSEQ + i0) * 1024) + h * 64 + lane * 2;
#pragma unroll
    for (int t = 0; t < 4; t++) {
        float inv = 1.0f / l[t];
        *(float2*)(op + t * 1024) = make_float2(ax[t] * inv, ay[t] * inv);
    }
}

// ---------------------------------------------------------------------------
// Launch sequence (graph-capturable: kernel launches only, default stream)
// Inputs: 0=x, 1=wq, 2=wk, 3=wv, 4=wo, 5=q_norm_w, 6=k_norm_w
// ---------------------------------------------------------------------------
extern "C" void kernel_launch(void* const* d_in, const int* in_sizes, int n_in,
                              void* d_out, int out_size)
{
    const float* x   = (const float*)d_in[0];
    const float* wq  = (const float*)d_in[1];
    const float* wk  = (const float*)d_in[2];
    const float* wv  = (const float*)d_in[3];
    const float* wo  = (const float*)d_in[4];
    const float* qnw = (const float*)d_in[5];
    const float* knw = (const float*)d_in[6];
    float* out = (float*)d_out;

    // 1) QKV projection (fused, tensor cores): grid (12, 32)
    qkv_kernel<<<dim3(12, 32), 256>>>(x, wq, wk, wv);

    // 2) RMSNorm q (folds attention scale 1/8)
    rmsnorm_kernel<<<(TOK * HQ * 32) / 256, 256>>>(qnw, 0, TOK * HQ, 0.125f);

    // 3) RMSNorm k
    rmsnorm_kernel<<<(TOK * HKV * 32) / 256, 256>>>(knw, 1, TOK * HKV, 1.0f);

    // 4) Sliding-window ALiBi attention
    attn_kernel<<<2048, 256>>>();

    // 5) Output projection (tensor cores): grid (8, 32)
    oproj_kernel<<<dim3(8, 32), 256>>>(wo, out);
}

// round 13
// speedup vs baseline: 2.2484x; 1.0641x over previous
#include <cuda_runtime.h>
#include <math.h>

// Problem constants
#define TOK   4096   // B*L = 2*2048
#define DIMK  1024
#define HQ    16
#define HKV   4
#define HD    64
#define LSEQ  2048

// Scratch (static device globals — allocation-free)
__device__ float g_q [TOK * HQ  * HD];   // 16 MB  [token][h*64+d]  (normed * 1/8)
__device__ float g_k [TOK * HKV * HD];   //  4 MB  [token][kv*64+d] (normed)
__device__ float g_v [TOK * HKV * HD];   //  4 MB
__device__ float g_ao[TOK * HQ  * HD];   // 16 MB  attention output

// ---------------------------------------------------------------------------
// tf32 helpers
// ---------------------------------------------------------------------------
__device__ __forceinline__ unsigned f2tf(float f) {
    unsigned r;
    asm("cvt.rna.tf32.f32 %0, %1;" : "=r"(r) : "f"(f));
    return r;
}

__device__ __forceinline__ void mma_tf32(float& c0, float& c1, float& c2, float& c3,
                                         unsigned a0, unsigned a1, unsigned a2, unsigned a3,
                                         unsigned b0, unsigned b1)
{
    asm volatile(
        "mma.sync.aligned.m16n8k8.row.col.f32.tf32.tf32.f32 "
        "{%0,%1,%2,%3}, {%4,%5,%6,%7}, {%8,%9}, {%0,%1,%2,%3};"
        : "+f"(c0), "+f"(c1), "+f"(c2), "+f"(c3)
        : "r"(a0), "r"(a1), "r"(a2), "r"(a3), "r"(b0), "r"(b1));
}

// ---------------------------------------------------------------------------
// 128x128 tile GEMM on tensor cores (tf32), C[m,n] = sum_k A[m,k]*B[n,k]
// (NT, both row-major, K contiguous). BK=32, double-buffered dynamic smem,
// 256 threads, 8 warps (4x2), each warp 32x64 via 2x8 m16n8k8 tiles.
// Optional fused per-head RMSNorm epilogue: each warp's 64-col span is one
// 64-dim head; each output row's 16 values live in a 4-lane quad.
// ---------------------------------------------------------------------------
#define SROW 36                    // padded row stride (words)
#define GHALF (128 * SROW)         // words per operand buffer
#define GSMEM_BYTES (4 * GHALF * 4)  // 2 buffers x (A+B) = 73728 B

__device__ __forceinline__ void gemm128_tc(const float* __restrict__ Ag,
                                           const float* __restrict__ Bg,
                                           float*       __restrict__ Cg,
                                           int K, int ldc,
                                           const float* __restrict__ nw,  // null = plain store
                                           float outScale)
{
    extern __shared__ unsigned sh[];   // [2][A|B][128*SROW]

    const int tid    = threadIdx.x;
    const int lane   = tid & 31;
    const int wid    = tid >> 5;
    const int warp_m = (wid & 3) * 32;
    const int warp_n = (wid >> 2) * 64;
    const int g      = lane >> 2;
    const int tig    = lane & 3;

    float acc[2][8][4];
#pragma unroll
    for (int mt = 0; mt < 2; mt++)
#pragma unroll
        for (int nt = 0; nt < 8; nt++)
#pragma unroll
            for (int c = 0; c < 4; c++) acc[mt][nt][c] = 0.0f;

    // Staging: each thread owns 16 consecutive floats of one row per operand.
    const int srow = tid >> 1;
    const int sc0  = (tid & 1) * 16;
    const float* Aptr = Ag + (size_t)srow * K + sc0;
    const float* Bptr = Bg + (size_t)srow * K + sc0;
    const int soff = srow * SROW + sc0;

    float4 ra[4], rb[4];
#pragma unroll
    for (int i = 0; i < 4; i++) {
        ra[i] = *(const float4*)(Aptr + i * 4);
        rb[i] = *(const float4*)(Bptr + i * 4);
    }
    // store slab 0 into buffer 0
    {
        unsigned* Asm = sh + soff;
        unsigned* Bsm = sh + GHALF + soff;
#pragma unroll
        for (int i = 0; i < 4; i++) {
            *(uint4*)(Asm + i * 4) = make_uint4(f2tf(ra[i].x), f2tf(ra[i].y), f2tf(ra[i].z), f2tf(ra[i].w));
            *(uint4*)(Bsm + i * 4) = make_uint4(f2tf(rb[i].x), f2tf(rb[i].y), f2tf(rb[i].z), f2tf(rb[i].w));
        }
    }
    __syncthreads();

    const int NS = K >> 5;   // slabs of 32
    for (int s = 0; s < NS; s++) {
        const int cur = s & 1;
        const unsigned* Ac = sh + cur * 2 * GHALF;
        const unsigned* Bc = Ac + GHALF;

        // Prefetch next slab into registers
        if (s + 1 < NS) {
            const int koff = (s + 1) << 5;
#pragma unroll
            for (int i = 0; i < 4; i++) {
                ra[i] = *(const float4*)(Aptr + koff + i * 4);
                rb[i] = *(const float4*)(Bptr + koff + i * 4);
            }
        }

        // Compute 4 k-steps of 8 from current buffer
#pragma unroll
        for (int ks = 0; ks < 4; ks++) {
            const int kk = ks * 8;
            unsigned a[2][4];
#pragma unroll
            for (int mt = 0; mt < 2; mt++) {
                const int mr = warp_m + mt * 16 + g;
                a[mt][0] = Ac[mr * SROW + kk + tig];
                a[mt][1] = Ac[(mr + 8) * SROW + kk + tig];
                a[mt][2] = Ac[mr * SROW + kk + tig + 4];
                a[mt][3] = Ac[(mr + 8) * SROW + kk + tig + 4];
            }
#pragma unroll
            for (int nt = 0; nt < 8; nt++) {
                const int nr = warp_n + nt * 8 + g;
                const unsigned b0 = Bc[nr * SROW + kk + tig];
                const unsigned b1 = Bc[nr * SROW + kk + tig + 4];
                mma_tf32(acc[0][nt][0], acc[0][nt][1], acc[0][nt][2], acc[0][nt][3],
                         a[0][0], a[0][1], a[0][2], a[0][3], b0, b1);
                mma_tf32(acc[1][nt][0], acc[1][nt][1], acc[1][nt][2], acc[1][nt][3],
                         a[1][0], a[1][1], a[1][2], a[1][3], b0, b1);
            }
        }

        // Store next slab into the other buffer
        if (s + 1 < NS) {
            unsigned* Asm = sh + (cur ^ 1) * 2 * GHALF + soff;
            unsigned* Bsm = Asm + GHALF;
#pragma unroll
            for (int i = 0; i < 4; i++) {
                *(uint4*)(Asm + i * 4) = make_uint4(f2tf(ra[i].x), f2tf(ra[i].y), f2tf(ra[i].z), f2tf(ra[i].w));
                *(uint4*)(Bsm + i * 4) = make_uint4(f2tf(rb[i].x), f2tf(rb[i].y), f2tf(rb[i].z), f2tf(rb[i].w));
            }
        }
        __syncthreads();
    }

    // ---------------- Epilogue ----------------
    if (nw == nullptr) {
#pragma unroll
        for (int mt = 0; mt < 2; mt++)
#pragma unroll
            for (int nt = 0; nt < 8; nt++) {
                const int r0 = warp_m + mt * 16 + g;
                const int c  = warp_n + nt * 8 + tig * 2;
                *(float2*)(Cg + (size_t)r0 * ldc + c)       = make_float2(acc[mt][nt][0], acc[mt][nt][1]);
                *(float2*)(Cg + (size_t)(r0 + 8) * ldc + c) = make_float2(acc[mt][nt][2], acc[mt][nt][3]);
            }
    } else {
        // Fused per-head RMSNorm: cols (warp_n + nt*8 + tig*2) map to head dim
        // (nt*8 + tig*2) since warp_n is a multiple of 64 and heads are 64-wide.
        float w[16];
#pragma unroll
        for (int nt = 0; nt < 8; nt++) {
            float2 ww = *(const float2*)(nw + nt * 8 + tig * 2);
            w[nt * 2]     = ww.x;
            w[nt * 2 + 1] = ww.y;
        }
#pragma unroll
        for (int mt = 0; mt < 2; mt++) {
            float s0 = 0.f, s1 = 0.f;
#pragma unroll
            for (int nt = 0; nt < 8; nt++) {
                s0 += acc[mt][nt][0] * acc[mt][nt][0] + acc[mt][nt][1] * acc[mt][nt][1];
                s1 += acc[mt][nt][2] * acc[mt][nt][2] + acc[mt][nt][3] * acc[mt][nt][3];
            }
            // reduce within the 4-lane quad (same g, tig 0..3)
            s0 += __shfl_xor_sync(0xffffffffu, s0, 1);
            s0 += __shfl_xor_sync(0xffffffffu, s0, 2);
            s1 += __shfl_xor_sync(0xffffffffu, s1, 1);
            s1 += __shfl_xor_sync(0xffffffffu, s1, 2);
            const float n0 = rsqrtf(s0 * (1.0f / 64.0f) + 0.01f) * outScale;
            const float n1 = rsqrtf(s1 * (1.0f / 64.0f) + 0.01f) * outScale;
            const int r0 = warp_m + mt * 16 + g;
#pragma unroll
            for (int nt = 0; nt < 8; nt++) {
                const int c = warp_n + nt * 8 + tig * 2;
                *(float2*)(Cg + (size_t)r0 * ldc + c) =
                    make_float2(acc[mt][nt][0] * n0 * w[nt * 2], acc[mt][nt][1] * n0 * w[nt * 2 + 1]);
                *(float2*)(Cg + (size_t)(r0 + 8) * ldc + c) =
                    make_float2(acc[mt][nt][2] * n1 * w[nt * 2], acc[mt][nt][3] * n1 * w[nt * 2 + 1]);
            }
        }
    }
}

// ---------------------------------------------------------------------------
// Fused QKV projection + per-head RMSNorm epilogue: grid (12, 32).
// N-blocks 0..7 -> q (norm, *1/8), 8..9 -> k (norm), 10..11 -> v (plain).
// ---------------------------------------------------------------------------
__global__ void __launch_bounds__(256, 2)
qkv_kernel(const float* __restrict__ x,  const float* __restrict__ wq,
           const float* __restrict__ wk, const float* __restrict__ wv,
           const float* __restrict__ qnw, const float* __restrict__ knw)
{
    const int nb = blockIdx.x;
    const int mb = blockIdx.y;
    const float* Bg;
    float* Cg;
    int ldc;
    const float* nw;
    float sc;
    if (nb < 8) {
        Bg  = wq + (size_t)nb * 128 * DIMK;
        Cg  = g_q + (size_t)mb * 128 * 1024 + nb * 128;
        ldc = 1024; nw = qnw; sc = 0.125f;     // fold softmax 1/sqrt(64)
    } else if (nb < 10) {
        int t = nb - 8;
        Bg  = wk + (size_t)t * 128 * DIMK;
        Cg  = g_k + (size_t)mb * 128 * 256 + t * 128;
        ldc = 256; nw = knw; sc = 1.0f;
    } else {
        int t = nb - 10;
        Bg  = wv + (size_t)t * 128 * DIMK;
        Cg  = g_v + (size_t)mb * 128 * 256 + t * 128;
        ldc = 256; nw = nullptr; sc = 1.0f;
    }
    gemm128_tc(x + (size_t)mb * 128 * DIMK, Bg, Cg, DIMK, ldc, nw, sc);
}

// ---------------------------------------------------------------------------
// Output projection: out = g_ao @ wo^T, grid (8, 32).
// ---------------------------------------------------------------------------
__global__ void __launch_bounds__(256, 2)
oproj_kernel(const float* __restrict__ wo, float* __restrict__ out)
{
    gemm128_tc(g_ao + (size_t)blockIdx.y * 128 * 1024,
               wo   + (size_t)blockIdx.x * 128 * DIMK,
               out  + (size_t)blockIdx.y * 128 * 1024 + blockIdx.x * 128,
               DIMK, 1024, nullptr, 1.0f);
}

// ---------------------------------------------------------------------------
// Sliding-window ALiBi attention, low-instruction-count layout.
// Warp = 4 queries of one (b,h), as four 8-lane groups (gid = lane>>3).
// Each lane owns 8 head dims (sub = lane&7 -> dims sub*8..sub*8+7).
// Dot = 8 FMA + 3 shfls within the group; online softmax per group; P*V
// accumulated in 8 registers per lane. q carries 1/sqrt(64) already.
// ---------------------------------------------------------------------------
__global__ void attn_kernel()
{
    const int gw   = (blockIdx.x * blockDim.x + threadIdx.x) >> 5;  // 0..16383
    const int lane = threadIdx.x & 31;
    const int gid  = lane >> 3;          // query within warp
    const int sub  = lane & 7;           // dim octet
    const int b   = gw >> 13;
    const int h   = (gw >> 9) & 15;
    const int i0  = (gw & 511) << 2;
    const int i   = i0 + gid;
    const int kvh = h & 3;

    const float slope = exp2f(-0.5f * (float)(h + 1));

    const float* qp = g_q + ((size_t)(b * LSEQ + i) * 1024) + h * 64 + sub * 8;
    const float4 q0 = *(const float4*)qp;
    const float4 q1 = *(const float4*)(qp + 4);

    const float* kp = g_k + (size_t)b * LSEQ * 256 + kvh * 64 + sub * 8;
    const float* vp = g_v + (size_t)b * LSEQ * 256 + kvh * 64 + sub * 8;

    float m = -1e30f, l = 0.0f;
    float o0 = 0.f, o1 = 0.f, o2 = 0.f, o3 = 0.f;
    float o4 = 0.f, o5 = 0.f, o6 = 0.f, o7 = 0.f;

    int jlo = i0 - 16; if (jlo < 0) jlo = 0;
    for (int j = jlo; j <= i0 + 3; j++) {
        const float* kr = kp + (size_t)j * 256;
        const float* vr = vp + (size_t)j * 256;
        const float4 k0 = *(const float4*)kr;
        const float4 k1 = *(const float4*)(kr + 4);
        const float4 v0 = *(const float4*)vr;
        const float4 v1 = *(const float4*)(vr + 4);

        float s = q0.x * k0.x + q0.y * k0.y + q0.z * k0.z + q0.w * k0.w
                + q1.x * k1.x + q1.y * k1.y + q1.z * k1.z + q1.w * k1.w;
        s += __shfl_xor_sync(0xffffffffu, s, 1);
        s += __shfl_xor_sync(0xffffffffu, s, 2);
        s += __shfl_xor_sync(0xffffffffu, s, 4);   // all 8 lanes of group have s

        const bool active = (j <= i) && (j >= i - 16);  // uniform within group
        if (active) {
            s += slope * (float)(j - i);           // ALiBi bias (<= 0)
            const float mn = fmaxf(m, s);
            const float c  = __expf(m - mn);
            const float p  = __expf(s - mn);
            l  = l * c + p;
            o0 = o0 * c + p * v0.x;  o1 = o1 * c + p * v0.y;
            o2 = o2 * c + p * v0.z;  o3 = o3 * c + p * v0.w;
            o4 = o4 * c + p * v1.x;  o5 = o5 * c + p * v1.y;
            o6 = o6 * c + p * v1.z;  o7 = o7 * c + p * v1.w;
            m = mn;
        }
    }

    const float inv = 1.0f / l;
    float* op = g_ao + ((size_t)(b * LSEQ + i) * 1024) + h * 64 + sub * 8;
    *(float4*)op       = make_float4(o0 * inv, o1 * inv, o2 * inv, o3 * inv);
    *(float4*)(op + 4) = make_float4(o4 * inv, o5 * inv, o6 * inv, o7 * inv);
}

// ---------------------------------------------------------------------------
// Launch sequence (graph-capturable: kernel launches only, default stream)
// Inputs: 0=x, 1=wq, 2=wk, 3=wv, 4=wo, 5=q_norm_w, 6=k_norm_w
// ---------------------------------------------------------------------------
extern "C" void kernel_launch(void* const* d_in, const int* in_sizes, int n_in,
                              void* d_out, int out_size)
{
    const float* x   = (const float*)d_in[0];
    const float* wq  = (const float*)d_in[1];
    const float* wk  = (const float*)d_in[2];
    const float* wv  = (const float*)d_in[3];
    const float* wo  = (const float*)d_in[4];
    const float* qnw = (const float*)d_in[5];
    const float* knw = (const float*)d_in[6];
    float* out = (float*)d_out;

    // Opt in to >48KB dynamic smem (host-side attribute, idempotent, not captured)
    cudaFuncSetAttribute((const void*)qkv_kernel,
                         cudaFuncAttributeMaxDynamicSharedMemorySize, GSMEM_BYTES);
    cudaFuncSetAttribute((const void*)oproj_kernel,
                         cudaFuncAttributeMaxDynamicSharedMemorySize, GSMEM_BYTES);

    // 1) QKV projection + fused RMSNorm epilogue (tensor cores)
    qkv_kernel<<<dim3(12, 32), 256, GSMEM_BYTES>>>(x, wq, wk, wv, qnw, knw);

    // 2) Sliding-window ALiBi attention
    attn_kernel<<<2048, 256>>>();

    // 3) Output projection (tensor cores)
    oproj_kernel<<<dim3(8, 32), 256, GSMEM_BYTES>>>(wo, out);
}